// round 7
// baseline (speedup 1.0000x reference)
#include <cuda_runtime.h>
#include <cuda_fp16.h>
#include <cstdint>

#define BATCH 8
#define SEQ   2048
#define HID   1024
#define NEG_INF_V (-1e9f)
#define LN_EPS 1e-12f

// ---------------- scratch (device globals: allocation-free) ----------------
// g_S holds fp16 scores (67 MB); later reused as fp32 context (64 MB fits).
__device__ __half g_S [(size_t)BATCH * SEQ * SEQ];
__device__ __half g_P [(size_t)BATCH * SEQ * SEQ];
__device__ __half g_Xb[(size_t)BATCH * SEQ * HID];   // inputs fp16 row-major
__device__ __half g_XT[(size_t)BATCH * HID * SEQ];   // inputs^T fp16
__device__ __half g_Qb[(size_t)BATCH * SEQ * HID];
__device__ __half g_Kb[(size_t)BATCH * SEQ * HID];
__device__ __half g_Wq[(size_t)HID * HID];           // Wq^T fp16 [N][K]
__device__ __half g_Wk[(size_t)HID * HID];           // Wk^T fp16 [N][K]

// ======================= helpers ===========================================
__device__ __forceinline__ uint32_t smem_u32(const void* p) {
    uint32_t a;
    asm("{ .reg .u64 t; cvta.to.shared.u64 t, %1; cvt.u32.u64 %0, t; }"
        : "=r"(a) : "l"(p));
    return a;
}
#define CP_ASYNC16(s, g) \
    asm volatile("cp.async.cg.shared.global [%0], [%1], 16;" :: "r"(s), "l"(g))
#define CP_COMMIT() asm volatile("cp.async.commit_group;")
#define CP_WAIT2()  asm volatile("cp.async.wait_group 2;")

#define LDSM4(r, addr) \
    asm volatile("ldmatrix.sync.aligned.m8n8.x4.shared.b16 {%0,%1,%2,%3}, [%4];" \
        : "=r"((r)[0]), "=r"((r)[1]), "=r"((r)[2]), "=r"((r)[3]) : "r"(addr))

#define MMA16816(d, a, b0, b1) \
    asm volatile("mma.sync.aligned.m16n8k16.row.col.f32.f16.f16.f32 " \
        "{%0,%1,%2,%3}, {%4,%5,%6,%7}, {%8,%9}, {%0,%1,%2,%3};" \
        : "+f"((d)[0]), "+f"((d)[1]), "+f"((d)[2]), "+f"((d)[3]) \
        : "r"((a)[0]), "r"((a)[1]), "r"((a)[2]), "r"((a)[3]), "r"(b0), "r"(b1))

// ======================= fp16 HMMA GEMM ====================================
// C[m,n] = sum_k A[m,k] * B[n,k]; A [M,K], B [N,K], fp16 K-major.
// 128x128 block tile, 8 warps (2x4), 64x32 per warp, 4-stage cp.async.
#define GBM 128
#define GBN 128
#define GBK 32
#define ROWB 80                       // 64B data + 16B pad per smem row
#define TILEB (128 * ROWB)            // 10240 B
#define STAGEB (2 * TILEB)            // A + B
#define SMEM_GEMM (4 * STAGEB)        // 81920 B -> 2 CTAs/SM (163840 <= 227KB)

#define OUT_F32 0
#define OUT_F16 1

template<int OUT, bool HAS_BIAS>
__global__ __launch_bounds__(256, 2)
void hgemm(const __half* __restrict__ A, const __half* __restrict__ B,
           const float* __restrict__ bias, void* __restrict__ Cv,
           int M, int N, int K,
           long long sA, long long sB, long long sC)
{
    extern __shared__ char sm[];
    const __half* Ab = A + (long long)blockIdx.z * sA;
    const __half* Bb = B + (long long)blockIdx.z * sB;

    const int bm = blockIdx.y * GBM;
    const int bn = blockIdx.x * GBN;
    const int tid = threadIdx.x;
    const int wid = tid >> 5, lane = tid & 31;
    const int wm = (wid >> 2) * 64;    // warp row offset (0 or 64)
    const int wn = (wid & 3) * 32;     // warp col offset (0..96)

    float acc[4][4][4];
    #pragma unroll
    for (int i = 0; i < 4; ++i)
        #pragma unroll
        for (int j = 0; j < 4; ++j)
            #pragma unroll
            for (int q = 0; q < 4; ++q) acc[i][j][q] = 0.f;

    const int NC = K / GBK;

    // ---- async tile loader (each thread: 2 A chunks + 2 B chunks of 16B) --
    auto issue = [&](int chunk, int stage) {
        char* base = sm + stage * STAGEB;
        const int k0 = chunk * GBK;
        #pragma unroll
        for (int i = 0; i < 2; ++i) {
            int cc  = tid + i * 256;         // 0..511
            int row = cc >> 2;               // 0..127
            int q   = cc & 3;                // 16B chunk within 64B row
            uint32_t sa = smem_u32(base + row * ROWB + q * 16);
            const void* ga = Ab + (long long)(bm + row) * K + k0 + q * 8;
            CP_ASYNC16(sa, ga);
            uint32_t sb = smem_u32(base + TILEB + row * ROWB + q * 16);
            const void* gb = Bb + (long long)(bn + row) * K + k0 + q * 8;
            CP_ASYNC16(sb, gb);
        }
    };

    // prologue: fill 3 stages
    issue(0, 0); CP_COMMIT();
    issue(1, 1); CP_COMMIT();
    issue(2, 2); CP_COMMIT();

    for (int c = 0; c < NC; ++c) {
        CP_WAIT2();            // chunk c resident (<=2 younger groups pending)
        __syncthreads();       // all warps done with stage being overwritten

        const int nc = c + 3;
        if (nc < NC) issue(nc, nc & 3);
        CP_COMMIT();           // empty group in tail keeps bookkeeping uniform

        const int stg = c & 3;
        const uint32_t abase = smem_u32(sm + stg * STAGEB);
        const uint32_t bbase = abase + TILEB;

        #pragma unroll
        for (int ks = 0; ks < 2; ++ks) {
            uint32_t a[4][4], b[2][4];
            #pragma unroll
            for (int t = 0; t < 4; ++t) {
                uint32_t addr = abase
                    + (uint32_t)(wm + t * 16 + (lane & 15)) * ROWB
                    + ks * 32 + ((lane >> 4) << 4);
                LDSM4(a[t], addr);
            }
            #pragma unroll
            for (int u = 0; u < 2; ++u) {
                uint32_t addr = bbase
                    + (uint32_t)(wn + u * 16 + ((lane >> 4) << 3) + (lane & 7)) * ROWB
                    + ks * 32 + (((lane >> 3) & 1) << 4);
                LDSM4(b[u], addr);
            }
            #pragma unroll
            for (int tm = 0; tm < 4; ++tm)
                #pragma unroll
                for (int j = 0; j < 4; ++j)
                    MMA16816(acc[tm][j], a[tm],
                             b[j >> 1][(j & 1) * 2], b[j >> 1][(j & 1) * 2 + 1]);
        }
    }

    // ---- epilogue: direct global stores ----
    const int qr = lane >> 2;            // 0..7
    const int qc = (lane & 3) * 2;       // 0,2,4,6
    #pragma unroll
    for (int tm = 0; tm < 4; ++tm) {
        #pragma unroll
        for (int j = 0; j < 4; ++j) {
            const long long n0 = bn + wn + j * 8 + qc;
            const long long m0 = bm + wm + tm * 16 + qr;
            float b0 = 0.f, b1 = 0.f;
            if (HAS_BIAS) { b0 = bias[n0]; b1 = bias[n0 + 1]; }
            if (OUT == OUT_F16) {
                __half* C = (__half*)Cv + (long long)blockIdx.z * sC;
                __half2 lo = __floats2half2_rn(acc[tm][j][0] + b0, acc[tm][j][1] + b1);
                __half2 hi = __floats2half2_rn(acc[tm][j][2] + b0, acc[tm][j][3] + b1);
                *reinterpret_cast<uint32_t*>(C + m0 * N + n0)       = *reinterpret_cast<uint32_t*>(&lo);
                *reinterpret_cast<uint32_t*>(C + (m0 + 8) * N + n0) = *reinterpret_cast<uint32_t*>(&hi);
            } else {
                float* C = (float*)Cv + (long long)blockIdx.z * sC;
                *reinterpret_cast<float2*>(C + m0 * N + n0) =
                    make_float2(acc[tm][j][0] + b0, acc[tm][j][1] + b1);
                *reinterpret_cast<float2*>(C + (m0 + 8) * N + n0) =
                    make_float2(acc[tm][j][2] + b0, acc[tm][j][3] + b1);
            }
        }
    }
}

// ------- fp32 [R,C] -> fp16 transpose [C,R]; optionally also row-major copy -
template<bool WROW>
__global__ __launch_bounds__(256)
void transpose_h_k(const float* __restrict__ in, __half* __restrict__ outT,
                   __half* __restrict__ outR,
                   int R, int C, long long sIn, long long sOutT, long long sOutR)
{
    __shared__ float t[32][33];
    const float* ib = in + (long long)blockIdx.z * sIn;
    __half* obT = outT + (long long)blockIdx.z * sOutT;
    int c0 = blockIdx.x * 32, r0 = blockIdx.y * 32;
    int tx = threadIdx.x & 31, ty = threadIdx.x >> 5;   // 32 x 8
    #pragma unroll
    for (int j = 0; j < 4; ++j) {
        float v = ib[(long long)(r0 + ty + j * 8) * C + c0 + tx];
        t[ty + j * 8][tx] = v;
        if (WROW) {
            __half* obR = outR + (long long)blockIdx.z * sOutR;
            obR[(long long)(r0 + ty + j * 8) * C + c0 + tx] = __float2half(v);
        }
    }
    __syncthreads();
    #pragma unroll
    for (int j = 0; j < 4; ++j)
        obT[(long long)(c0 + ty + j * 8) * R + r0 + tx] =
            __float2half(t[tx][ty + j * 8]);
}

// ---------------- masked + scaled softmax: fp16 in, fp16 out ---------------
__global__ __launch_bounds__(256)
void softmax_k(const __half* __restrict__ S, __half* __restrict__ P,
               const int* __restrict__ masks, float scale)
{
    const size_t row = blockIdx.x;
    const int b = (int)(row >> 11);               // row / SEQ
    const __half* p = S + row * (size_t)SEQ;
    __half* o = P + row * (size_t)SEQ;
    const int* mrow = masks + (size_t)b * SEQ;
    const int k0 = threadIdx.x * 8;

    __shared__ float red[256];
    float v[8];
    {
        uint4 raw = *reinterpret_cast<const uint4*>(p + k0);
        const __half2* h2 = reinterpret_cast<const __half2*>(&raw);
        int4 m0 = *reinterpret_cast<const int4*>(mrow + k0);
        int4 m1 = *reinterpret_cast<const int4*>(mrow + k0 + 4);
        float2 f;
        f = __half22float2(h2[0]);
        v[0] = m0.x ? f.x * scale : NEG_INF_V;
        v[1] = m0.y ? f.y * scale : NEG_INF_V;
        f = __half22float2(h2[1]);
        v[2] = m0.z ? f.x * scale : NEG_INF_V;
        v[3] = m0.w ? f.y * scale : NEG_INF_V;
        f = __half22float2(h2[2]);
        v[4] = m1.x ? f.x * scale : NEG_INF_V;
        v[5] = m1.y ? f.y * scale : NEG_INF_V;
        f = __half22float2(h2[3]);
        v[6] = m1.z ? f.x * scale : NEG_INF_V;
        v[7] = m1.w ? f.y * scale : NEG_INF_V;
    }
    float mx = -3e38f;
    #pragma unroll
    for (int i = 0; i < 8; ++i) mx = fmaxf(mx, v[i]);
    red[threadIdx.x] = mx;
    __syncthreads();
    #pragma unroll
    for (int s2 = 128; s2 > 0; s2 >>= 1) {
        if (threadIdx.x < s2)
            red[threadIdx.x] = fmaxf(red[threadIdx.x], red[threadIdx.x + s2]);
        __syncthreads();
    }
    mx = red[0];
    __syncthreads();

    float sum = 0.f;
    #pragma unroll
    for (int i = 0; i < 8; ++i) { v[i] = __expf(v[i] - mx); sum += v[i]; }
    red[threadIdx.x] = sum;
    __syncthreads();
    #pragma unroll
    for (int s2 = 128; s2 > 0; s2 >>= 1) {
        if (threadIdx.x < s2) red[threadIdx.x] += red[threadIdx.x + s2];
        __syncthreads();
    }
    const float inv = 1.0f / red[0];

    uint4 pk;
    __half2* ph = reinterpret_cast<__half2*>(&pk);
    ph[0] = __floats2half2_rn(v[0] * inv, v[1] * inv);
    ph[1] = __floats2half2_rn(v[2] * inv, v[3] * inv);
    ph[2] = __floats2half2_rn(v[4] * inv, v[5] * inv);
    ph[3] = __floats2half2_rn(v[6] * inv, v[7] * inv);
    *reinterpret_cast<uint4*>(o + k0) = pk;
}

// ---------------- residual + LayerNorm -------------------------------------
__global__ __launch_bounds__(256)
void ln_k(const float* __restrict__ X, const float* __restrict__ Cx,
          const float* __restrict__ gamma, const float* __restrict__ beta,
          float* __restrict__ out)
{
    const size_t row = blockIdx.x;
    const float* x = X  + row * (size_t)HID;
    const float* c = Cx + row * (size_t)HID;

    __shared__ float red[256];
    float v[4];
    float s = 0.f;
    #pragma unroll
    for (int i = 0; i < 4; ++i) {
        int k = threadIdx.x + i * 256;
        v[i] = x[k] + c[k];
        s += v[i];
    }
    red[threadIdx.x] = s;
    __syncthreads();
    #pragma unroll
    for (int s2 = 128; s2 > 0; s2 >>= 1) {
        if (threadIdx.x < s2) red[threadIdx.x] += red[threadIdx.x + s2];
        __syncthreads();
    }
    const float mu = red[0] * (1.0f / HID);
    __syncthreads();

    float s2v = 0.f;
    #pragma unroll
    for (int i = 0; i < 4; ++i) { float d = v[i] - mu; s2v += d * d; }
    red[threadIdx.x] = s2v;
    __syncthreads();
    #pragma unroll
    for (int s2 = 128; s2 > 0; s2 >>= 1) {
        if (threadIdx.x < s2) red[threadIdx.x] += red[threadIdx.x + s2];
        __syncthreads();
    }
    const float var = red[0] * (1.0f / HID);
    const float r = rsqrtf(var + LN_EPS);
    #pragma unroll
    for (int i = 0; i < 4; ++i) {
        int k = threadIdx.x + i * 256;
        out[row * (size_t)HID + k] = (v[i] - mu) * r * gamma[k] + beta[k];
    }
}

// ---------------- launch ---------------------------------------------------
extern "C" void kernel_launch(void* const* d_in, const int* in_sizes, int n_in,
                              void* d_out, int out_size)
{
    const float* inputs = (const float*)d_in[0];
    const int*   masks  = (const int*)  d_in[1];
    const float* Wq     = (const float*)d_in[2];
    const float* bq     = (const float*)d_in[3];
    const float* Wk     = (const float*)d_in[4];
    const float* bk     = (const float*)d_in[5];
    const float* gamma  = (const float*)d_in[6];
    const float* beta   = (const float*)d_in[7];
    float* out = (float*)d_out;

    __half *Sp, *Pp, *Xbp, *XTp, *Qp, *Kp, *Wqp, *Wkp;
    cudaGetSymbolAddress((void**)&Sp,  g_S);
    cudaGetSymbolAddress((void**)&Pp,  g_P);
    cudaGetSymbolAddress((void**)&Xbp, g_Xb);
    cudaGetSymbolAddress((void**)&XTp, g_XT);
    cudaGetSymbolAddress((void**)&Qp,  g_Qb);
    cudaGetSymbolAddress((void**)&Kp,  g_Kb);
    cudaGetSymbolAddress((void**)&Wqp, g_Wq);
    cudaGetSymbolAddress((void**)&Wkp, g_Wk);
    float* Ctx = (float*)Sp;                         // context reuses scores mem

    const int M = BATCH * SEQ;                       // 16384
    const long long sSH = (long long)SEQ * HID;
    const long long sSS = (long long)SEQ * SEQ;
    const long long sHS = (long long)HID * SEQ;
    const float scale = 0.03125f;                    // 1/sqrt(1024)

    cudaFuncSetAttribute(hgemm<OUT_F16, true >, cudaFuncAttributeMaxDynamicSharedMemorySize, SMEM_GEMM);
    cudaFuncSetAttribute(hgemm<OUT_F16, false>, cudaFuncAttributeMaxDynamicSharedMemorySize, SMEM_GEMM);
    cudaFuncSetAttribute(hgemm<OUT_F32, false>, cudaFuncAttributeMaxDynamicSharedMemorySize, SMEM_GEMM);

    // fp16 conversions / transposes (X: both layouts in one pass)
    transpose_h_k<true ><<<dim3(HID/32, SEQ/32, BATCH), 256>>>(
        inputs, XTp, Xbp, SEQ, HID, sSH, sHS, sSH);
    transpose_h_k<false><<<dim3(HID/32, HID/32, 1), 256>>>(
        Wq, Wqp, nullptr, HID, HID, 0, 0, 0);
    transpose_h_k<false><<<dim3(HID/32, HID/32, 1), 256>>>(
        Wk, Wkp, nullptr, HID, HID, 0, 0, 0);

    // Q = X Wq + bq ; K = X Wk + bk  -> fp16
    hgemm<OUT_F16, true><<<dim3(HID/GBN, M/GBM, 1), 256, SMEM_GEMM>>>(
        Xbp, Wqp, bq, Qp, M, HID, HID, 0, 0, 0);
    hgemm<OUT_F16, true><<<dim3(HID/GBN, M/GBM, 1), 256, SMEM_GEMM>>>(
        Xbp, Wkp, bk, Kp, M, HID, HID, 0, 0, 0);

    // scores = Q K^T per batch -> fp16
    hgemm<OUT_F16, false><<<dim3(SEQ/GBN, SEQ/GBM, BATCH), 256, SMEM_GEMM>>>(
        Qp, Kp, nullptr, Sp, SEQ, SEQ, HID, sSH, sSH, sSS);

    // masked, scaled softmax -> fp16 probs
    softmax_k<<<M, 256>>>(Sp, Pp, masks, scale);

    // context = probs @ X per batch -> fp32 (reuses scores memory)
    hgemm<OUT_F32, false><<<dim3(HID/GBN, SEQ/GBM, BATCH), 256, SMEM_GEMM>>>(
        Pp, XTp, nullptr, Ctx, SEQ, HID, SEQ, sSS, sHS, sSH);

    // out = LN(X + context)
    ln_k<<<M, 256>>>(inputs, Ctx, gamma, beta, out);
}

// round 8
// speedup vs baseline: 1.5182x; 1.5182x over previous
#include <cuda_runtime.h>
#include <cuda_fp16.h>
#include <cstdint>

#define BATCH 8
#define SEQ   2048
#define HID   1024
#define NEG_INF_V (-1e9f)
#define LN_EPS 1e-12f

// ---------------- scratch (device globals: allocation-free) ----------------
// g_S holds fp16 scores (67 MB); later reused as fp32 context (64 MB fits).
__device__ __half g_S [(size_t)BATCH * SEQ * SEQ];
__device__ __half g_P [(size_t)BATCH * SEQ * SEQ];
__device__ __half g_Xb[(size_t)BATCH * SEQ * HID];   // inputs fp16 row-major
__device__ __half g_XT[(size_t)BATCH * HID * SEQ];   // inputs^T fp16
__device__ __half g_Qb[(size_t)BATCH * SEQ * HID];
__device__ __half g_Kb[(size_t)BATCH * SEQ * HID];
__device__ __half g_Wq[(size_t)HID * HID];           // Wq^T fp16 [N][K]
__device__ __half g_Wk[(size_t)HID * HID];           // Wk^T fp16 [N][K]

// ======================= helpers ===========================================
__device__ __forceinline__ uint32_t smem_u32(const void* p) {
    uint32_t a;
    asm("{ .reg .u64 t; cvta.to.shared.u64 t, %1; cvt.u32.u64 %0, t; }"
        : "=r"(a) : "l"(p));
    return a;
}
#define CP_ASYNC16(s, g) \
    asm volatile("cp.async.cg.shared.global [%0], [%1], 16;" :: "r"(s), "l"(g))
#define CP_COMMIT() asm volatile("cp.async.commit_group;")
#define CP_WAIT1()  asm volatile("cp.async.wait_group 1;")

#define LDSM4(r, addr) \
    asm volatile("ldmatrix.sync.aligned.m8n8.x4.shared.b16 {%0,%1,%2,%3}, [%4];" \
        : "=r"((r)[0]), "=r"((r)[1]), "=r"((r)[2]), "=r"((r)[3]) : "r"(addr))

#define MMA16816(d, a, b0, b1) \
    asm volatile("mma.sync.aligned.m16n8k16.row.col.f32.f16.f16.f32 " \
        "{%0,%1,%2,%3}, {%4,%5,%6,%7}, {%8,%9}, {%0,%1,%2,%3};" \
        : "+f"((d)[0]), "+f"((d)[1]), "+f"((d)[2]), "+f"((d)[3]) \
        : "r"((a)[0]), "r"((a)[1]), "r"((a)[2]), "r"((a)[3]), "r"(b0), "r"(b1))

// ======================= fp16 HMMA GEMM ====================================
// C[m,n] = sum_k A[m,k] * B[n,k]; A [M,K], B [N,K], fp16 K-major.
// 128x128 block tile, 8 warps (2x4), 64x32 per warp, 3-stage cp.async.
// EXACT pipeline structure of the 768us round-5 winner.
#define GBM 128
#define GBN 128
#define GBK 32
#define ROWB 80                       // 64B data + 16B pad per smem row
#define TILEB (128 * ROWB)            // 10240 B
#define STAGEB (2 * TILEB)            // A + B
#define SMEM_GEMM (3 * STAGEB)        // 61440 B -> 2 CTAs/SM

#define OUT_F32 0
#define OUT_F16 1

template<int OUT, bool HAS_BIAS>
__global__ __launch_bounds__(256, 2)
void hgemm(const __half* __restrict__ A, const __half* __restrict__ B,
           const float* __restrict__ bias, void* __restrict__ Cv,
           int M, int N, int K,
           long long sA, long long sB, long long sC)
{
    extern __shared__ char sm[];
    const __half* Ab = A + (long long)blockIdx.z * sA;
    const __half* Bb = B + (long long)blockIdx.z * sB;

    const int bm = blockIdx.y * GBM;
    const int bn = blockIdx.x * GBN;
    const int tid = threadIdx.x;
    const int wid = tid >> 5, lane = tid & 31;
    const int wm = (wid >> 2) * 64;    // warp row offset (0 or 64)
    const int wn = (wid & 3) * 32;     // warp col offset (0..96)

    float acc[4][4][4];
    #pragma unroll
    for (int i = 0; i < 4; ++i)
        #pragma unroll
        for (int j = 0; j < 4; ++j)
            #pragma unroll
            for (int q = 0; q < 4; ++q) acc[i][j][q] = 0.f;

    const int NC = K / GBK;

    // ---- async tile loader (each thread: 2 A chunks + 2 B chunks of 16B) --
    auto issue = [&](int chunk, int stage) {
        char* base = sm + stage * STAGEB;
        const int k0 = chunk * GBK;
        #pragma unroll
        for (int i = 0; i < 2; ++i) {
            int cc  = tid + i * 256;         // 0..511
            int row = cc >> 2;               // 0..127
            int q   = cc & 3;                // 16B chunk within 64B row
            uint32_t sa = smem_u32(base + row * ROWB + q * 16);
            const void* ga = Ab + (long long)(bm + row) * K + k0 + q * 8;
            CP_ASYNC16(sa, ga);
            uint32_t sb = smem_u32(base + TILEB + row * ROWB + q * 16);
            const void* gb = Bb + (long long)(bn + row) * K + k0 + q * 8;
            CP_ASYNC16(sb, gb);
        }
    };

    // prologue: fill 2 stages
    issue(0, 0); CP_COMMIT();
    issue(1, 1); CP_COMMIT();

    for (int c = 0; c < NC; ++c) {
        CP_WAIT1();            // chunk c resident
        __syncthreads();       // all warps see it; stage (c+2)%3 fully drained

        // prefetch chunk c+2 into the stage consumed at iter c-1
        const int nc = c + 2;
        if (nc < NC) issue(nc, nc % 3);
        CP_COMMIT();           // empty group in tail keeps bookkeeping uniform

        const int stg = c % 3;
        const uint32_t abase = smem_u32(sm + stg * STAGEB);
        const uint32_t bbase = abase + TILEB;

        #pragma unroll
        for (int ks = 0; ks < 2; ++ks) {
            uint32_t a[4][4], b[2][4];
            #pragma unroll
            for (int t = 0; t < 4; ++t) {
                uint32_t addr = abase
                    + (uint32_t)(wm + t * 16 + (lane & 15)) * ROWB
                    + ks * 32 + ((lane >> 4) << 4);
                LDSM4(a[t], addr);
            }
            #pragma unroll
            for (int u = 0; u < 2; ++u) {
                uint32_t addr = bbase
                    + (uint32_t)(wn + u * 16 + ((lane >> 4) << 3) + (lane & 7)) * ROWB
                    + ks * 32 + (((lane >> 3) & 1) << 4);
                LDSM4(b[u], addr);
            }
            #pragma unroll
            for (int tm = 0; tm < 4; ++tm)
                #pragma unroll
                for (int j = 0; j < 4; ++j)
                    MMA16816(acc[tm][j], a[tm],
                             b[j >> 1][(j & 1) * 2], b[j >> 1][(j & 1) * 2 + 1]);
        }
    }

    // ---- epilogue: direct global stores ----
    const int qr = lane >> 2;            // 0..7
    const int qc = (lane & 3) * 2;       // 0,2,4,6
    #pragma unroll
    for (int tm = 0; tm < 4; ++tm) {
        #pragma unroll
        for (int j = 0; j < 4; ++j) {
            const long long n0 = bn + wn + j * 8 + qc;
            const long long m0 = bm + wm + tm * 16 + qr;
            float b0 = 0.f, b1 = 0.f;
            if (HAS_BIAS) { b0 = bias[n0]; b1 = bias[n0 + 1]; }
            if (OUT == OUT_F16) {
                __half* C = (__half*)Cv + (long long)blockIdx.z * sC;
                __half2 lo = __floats2half2_rn(acc[tm][j][0] + b0, acc[tm][j][1] + b1);
                __half2 hi = __floats2half2_rn(acc[tm][j][2] + b0, acc[tm][j][3] + b1);
                *reinterpret_cast<uint32_t*>(C + m0 * N + n0)       = *reinterpret_cast<uint32_t*>(&lo);
                *reinterpret_cast<uint32_t*>(C + (m0 + 8) * N + n0) = *reinterpret_cast<uint32_t*>(&hi);
            } else {
                float* C = (float*)Cv + (long long)blockIdx.z * sC;
                *reinterpret_cast<float2*>(C + m0 * N + n0) =
                    make_float2(acc[tm][j][0] + b0, acc[tm][j][1] + b1);
                *reinterpret_cast<float2*>(C + (m0 + 8) * N + n0) =
                    make_float2(acc[tm][j][2] + b0, acc[tm][j][3] + b1);
            }
        }
    }
}

// ------- fp32 [R,C] -> fp16 transpose [C,R]; optionally also row-major copy -
template<bool WROW>
__global__ __launch_bounds__(256)
void transpose_h_k(const float* __restrict__ in, __half* __restrict__ outT,
                   __half* __restrict__ outR,
                   int R, int C, long long sIn, long long sOutT, long long sOutR)
{
    __shared__ float t[32][33];
    const float* ib = in + (long long)blockIdx.z * sIn;
    __half* obT = outT + (long long)blockIdx.z * sOutT;
    int c0 = blockIdx.x * 32, r0 = blockIdx.y * 32;
    int tx = threadIdx.x & 31, ty = threadIdx.x >> 5;   // 32 x 8
    #pragma unroll
    for (int j = 0; j < 4; ++j) {
        float v = ib[(long long)(r0 + ty + j * 8) * C + c0 + tx];
        t[ty + j * 8][tx] = v;
        if (WROW) {
            __half* obR = outR + (long long)blockIdx.z * sOutR;
            obR[(long long)(r0 + ty + j * 8) * C + c0 + tx] = __float2half(v);
        }
    }
    __syncthreads();
    #pragma unroll
    for (int j = 0; j < 4; ++j)
        obT[(long long)(c0 + ty + j * 8) * R + r0 + tx] =
            __float2half(t[tx][ty + j * 8]);
}

// ---------------- masked + scaled softmax: fp16 in, fp16 out ---------------
__global__ __launch_bounds__(256)
void softmax_k(const __half* __restrict__ S, __half* __restrict__ P,
               const int* __restrict__ masks, float scale)
{
    const size_t row = blockIdx.x;
    const int b = (int)(row >> 11);               // row / SEQ
    const __half* p = S + row * (size_t)SEQ;
    __half* o = P + row * (size_t)SEQ;
    const int* mrow = masks + (size_t)b * SEQ;
    const int k0 = threadIdx.x * 8;

    __shared__ float red[256];
    float v[8];
    {
        uint4 raw = *reinterpret_cast<const uint4*>(p + k0);
        const __half2* h2 = reinterpret_cast<const __half2*>(&raw);
        int4 m0 = *reinterpret_cast<const int4*>(mrow + k0);
        int4 m1 = *reinterpret_cast<const int4*>(mrow + k0 + 4);
        float2 f;
        f = __half22float2(h2[0]);
        v[0] = m0.x ? f.x * scale : NEG_INF_V;
        v[1] = m0.y ? f.y * scale : NEG_INF_V;
        f = __half22float2(h2[1]);
        v[2] = m0.z ? f.x * scale : NEG_INF_V;
        v[3] = m0.w ? f.y * scale : NEG_INF_V;
        f = __half22float2(h2[2]);
        v[4] = m1.x ? f.x * scale : NEG_INF_V;
        v[5] = m1.y ? f.y * scale : NEG_INF_V;
        f = __half22float2(h2[3]);
        v[6] = m1.z ? f.x * scale : NEG_INF_V;
        v[7] = m1.w ? f.y * scale : NEG_INF_V;
    }
    float mx = -3e38f;
    #pragma unroll
    for (int i = 0; i < 8; ++i) mx = fmaxf(mx, v[i]);
    red[threadIdx.x] = mx;
    __syncthreads();
    #pragma unroll
    for (int s2 = 128; s2 > 0; s2 >>= 1) {
        if (threadIdx.x < s2)
            red[threadIdx.x] = fmaxf(red[threadIdx.x], red[threadIdx.x + s2]);
        __syncthreads();
    }
    mx = red[0];
    __syncthreads();

    float sum = 0.f;
    #pragma unroll
    for (int i = 0; i < 8; ++i) { v[i] = __expf(v[i] - mx); sum += v[i]; }
    red[threadIdx.x] = sum;
    __syncthreads();
    #pragma unroll
    for (int s2 = 128; s2 > 0; s2 >>= 1) {
        if (threadIdx.x < s2) red[threadIdx.x] += red[threadIdx.x + s2];
        __syncthreads();
    }
    const float inv = 1.0f / red[0];

    uint4 pk;
    __half2* ph = reinterpret_cast<__half2*>(&pk);
    ph[0] = __floats2half2_rn(v[0] * inv, v[1] * inv);
    ph[1] = __floats2half2_rn(v[2] * inv, v[3] * inv);
    ph[2] = __floats2half2_rn(v[4] * inv, v[5] * inv);
    ph[3] = __floats2half2_rn(v[6] * inv, v[7] * inv);
    *reinterpret_cast<uint4*>(o + k0) = pk;
}

// ---------------- residual + LayerNorm -------------------------------------
__global__ __launch_bounds__(256)
void ln_k(const float* __restrict__ X, const float* __restrict__ Cx,
          const float* __restrict__ gamma, const float* __restrict__ beta,
          float* __restrict__ out)
{
    const size_t row = blockIdx.x;
    const float* x = X  + row * (size_t)HID;
    const float* c = Cx + row * (size_t)HID;

    __shared__ float red[256];
    float v[4];
    float s = 0.f;
    #pragma unroll
    for (int i = 0; i < 4; ++i) {
        int k = threadIdx.x + i * 256;
        v[i] = x[k] + c[k];
        s += v[i];
    }
    red[threadIdx.x] = s;
    __syncthreads();
    #pragma unroll
    for (int s2 = 128; s2 > 0; s2 >>= 1) {
        if (threadIdx.x < s2) red[threadIdx.x] += red[threadIdx.x + s2];
        __syncthreads();
    }
    const float mu = red[0] * (1.0f / HID);
    __syncthreads();

    float s2v = 0.f;
    #pragma unroll
    for (int i = 0; i < 4; ++i) { float d = v[i] - mu; s2v += d * d; }
    red[threadIdx.x] = s2v;
    __syncthreads();
    #pragma unroll
    for (int s2 = 128; s2 > 0; s2 >>= 1) {
        if (threadIdx.x < s2) red[threadIdx.x] += red[threadIdx.x + s2];
        __syncthreads();
    }
    const float var = red[0] * (1.0f / HID);
    const float r = rsqrtf(var + LN_EPS);
    #pragma unroll
    for (int i = 0; i < 4; ++i) {
        int k = threadIdx.x + i * 256;
        out[row * (size_t)HID + k] = (v[i] - mu) * r * gamma[k] + beta[k];
    }
}

// ---------------- launch ---------------------------------------------------
extern "C" void kernel_launch(void* const* d_in, const int* in_sizes, int n_in,
                              void* d_out, int out_size)
{
    const float* inputs = (const float*)d_in[0];
    const int*   masks  = (const int*)  d_in[1];
    const float* Wq     = (const float*)d_in[2];
    const float* bq     = (const float*)d_in[3];
    const float* Wk     = (const float*)d_in[4];
    const float* bk     = (const float*)d_in[5];
    const float* gamma  = (const float*)d_in[6];
    const float* beta   = (const float*)d_in[7];
    float* out = (float*)d_out;

    __half *Sp, *Pp, *Xbp, *XTp, *Qp, *Kp, *Wqp, *Wkp;
    cudaGetSymbolAddress((void**)&Sp,  g_S);
    cudaGetSymbolAddress((void**)&Pp,  g_P);
    cudaGetSymbolAddress((void**)&Xbp, g_Xb);
    cudaGetSymbolAddress((void**)&XTp, g_XT);
    cudaGetSymbolAddress((void**)&Qp,  g_Qb);
    cudaGetSymbolAddress((void**)&Kp,  g_Kb);
    cudaGetSymbolAddress((void**)&Wqp, g_Wq);
    cudaGetSymbolAddress((void**)&Wkp, g_Wk);
    float* Ctx = (float*)Sp;                         // context reuses scores mem

    const int M = BATCH * SEQ;                       // 16384
    const long long sSH = (long long)SEQ * HID;
    const long long sSS = (long long)SEQ * SEQ;
    const long long sHS = (long long)HID * SEQ;
    const float scale = 0.03125f;                    // 1/sqrt(1024)

    cudaFuncSetAttribute(hgemm<OUT_F16, true >, cudaFuncAttributeMaxDynamicSharedMemorySize, SMEM_GEMM);
    cudaFuncSetAttribute(hgemm<OUT_F16, false>, cudaFuncAttributeMaxDynamicSharedMemorySize, SMEM_GEMM);
    cudaFuncSetAttribute(hgemm<OUT_F32, false>, cudaFuncAttributeMaxDynamicSharedMemorySize, SMEM_GEMM);

    // fp16 conversions / transposes (X: both layouts in one pass)
    transpose_h_k<true ><<<dim3(HID/32, SEQ/32, BATCH), 256>>>(
        inputs, XTp, Xbp, SEQ, HID, sSH, sHS, sSH);
    transpose_h_k<false><<<dim3(HID/32, HID/32, 1), 256>>>(
        Wq, Wqp, nullptr, HID, HID, 0, 0, 0);
    transpose_h_k<false><<<dim3(HID/32, HID/32, 1), 256>>>(
        Wk, Wkp, nullptr, HID, HID, 0, 0, 0);

    // Q = X Wq + bq ; K = X Wk + bk  -> fp16
    hgemm<OUT_F16, true><<<dim3(HID/GBN, M/GBM, 1), 256, SMEM_GEMM>>>(
        Xbp, Wqp, bq, Qp, M, HID, HID, 0, 0, 0);
    hgemm<OUT_F16, true><<<dim3(HID/GBN, M/GBM, 1), 256, SMEM_GEMM>>>(
        Xbp, Wkp, bk, Kp, M, HID, HID, 0, 0, 0);

    // scores = Q K^T per batch -> fp16
    hgemm<OUT_F16, false><<<dim3(SEQ/GBN, SEQ/GBM, BATCH), 256, SMEM_GEMM>>>(
        Qp, Kp, nullptr, Sp, SEQ, SEQ, HID, sSH, sSH, sSS);

    // masked, scaled softmax -> fp16 probs
    softmax_k<<<M, 256>>>(Sp, Pp, masks, scale);

    // context = probs @ X per batch -> fp32 (reuses scores memory)
    hgemm<OUT_F32, false><<<dim3(HID/GBN, SEQ/GBM, BATCH), 256, SMEM_GEMM>>>(
        Pp, XTp, nullptr, Ctx, SEQ, HID, SEQ, sSS, sHS, sSH);

    // out = LN(X + context)
    ln_k<<<M, 256>>>(inputs, Ctx, gamma, beta, out);
}

// round 9
// speedup vs baseline: 1.6183x; 1.0659x over previous
#include <cuda_runtime.h>
#include <cuda_fp16.h>
#include <cstdint>

#define BATCH 8
#define SEQ   2048
#define HID   1024
#define NEG_INF_V (-1e9f)
#define LN_EPS 1e-12f

// ---------------- scratch (device globals: allocation-free) ----------------
// g_S holds fp16 scores (67 MB); later reused as fp32 context (64 MB fits).
__device__ __half g_S [(size_t)BATCH * SEQ * SEQ];
__device__ __half g_P [(size_t)BATCH * SEQ * SEQ];
__device__ __half g_Xb[(size_t)BATCH * SEQ * HID];   // inputs fp16 row-major
__device__ __half g_XT[(size_t)BATCH * HID * SEQ];   // inputs^T fp16
__device__ __half g_Qb[(size_t)BATCH * SEQ * HID];
__device__ __half g_Kb[(size_t)BATCH * SEQ * HID];
__device__ __half g_Wq[(size_t)HID * HID];           // Wq^T fp16 [N][K]
__device__ __half g_Wk[(size_t)HID * HID];           // Wk^T fp16 [N][K]

// ======================= helpers ===========================================
__device__ __forceinline__ uint32_t smem_u32(const void* p) {
    uint32_t a;
    asm("{ .reg .u64 t; cvta.to.shared.u64 t, %1; cvt.u32.u64 %0, t; }"
        : "=r"(a) : "l"(p));
    return a;
}
#define CP_ASYNC16(s, g) \
    asm volatile("cp.async.cg.shared.global [%0], [%1], 16;" :: "r"(s), "l"(g))
#define CP_COMMIT() asm volatile("cp.async.commit_group;")
#define CP_WAIT1()  asm volatile("cp.async.wait_group 1;")

#define LDSM4(r, addr) \
    asm volatile("ldmatrix.sync.aligned.m8n8.x4.shared.b16 {%0,%1,%2,%3}, [%4];" \
        : "=r"((r)[0]), "=r"((r)[1]), "=r"((r)[2]), "=r"((r)[3]) : "r"(addr))

#define MMA16816(d, a, b0, b1) \
    asm volatile("mma.sync.aligned.m16n8k16.row.col.f32.f16.f16.f32 " \
        "{%0,%1,%2,%3}, {%4,%5,%6,%7}, {%8,%9}, {%0,%1,%2,%3};" \
        : "+f"((d)[0]), "+f"((d)[1]), "+f"((d)[2]), "+f"((d)[3]) \
        : "r"((a)[0]), "r"((a)[1]), "r"((a)[2]), "r"((a)[3]), "r"(b0), "r"(b1))

// ======================= fp16 HMMA GEMM ====================================
// C[m,n] = sum_k A[m,k] * B[n,k]; A [M,K], B [N,K], fp16 K-major.
// 128x128 block tile, 8 warps (2x4), 64x32 per warp, 3-stage cp.async.
// GBK=64: half the barriers of the GBK=32 config, same registers.
#define GBM 128
#define GBN 128
#define GBK 64
#define ROWB 144                      // 128B data + 16B pad per smem row
#define TILEB (128 * ROWB)            // 18432 B
#define STAGEB (2 * TILEB)            // A + B
#define SMEM_GEMM (3 * STAGEB)        // 110592 B -> 2 CTAs/SM (221184 B)

#define OUT_F32 0
#define OUT_F16 1

template<int OUT, bool HAS_BIAS>
__global__ __launch_bounds__(256, 2)
void hgemm(const __half* __restrict__ A, const __half* __restrict__ B,
           const float* __restrict__ bias, void* __restrict__ Cv,
           int M, int N, int K,
           long long sA, long long sB, long long sC)
{
    extern __shared__ char sm[];
    const __half* Ab = A + (long long)blockIdx.z * sA;
    const __half* Bb = B + (long long)blockIdx.z * sB;

    const int bm = blockIdx.y * GBM;
    const int bn = blockIdx.x * GBN;
    const int tid = threadIdx.x;
    const int wid = tid >> 5, lane = tid & 31;
    const int wm = (wid >> 2) * 64;    // warp row offset (0 or 64)
    const int wn = (wid & 3) * 32;     // warp col offset (0..96)

    float acc[4][4][4];
    #pragma unroll
    for (int i = 0; i < 4; ++i)
        #pragma unroll
        for (int j = 0; j < 4; ++j)
            #pragma unroll
            for (int q = 0; q < 4; ++q) acc[i][j][q] = 0.f;

    const int NC = K / GBK;

    // ---- async tile loader (each thread: 4 A chunks + 4 B chunks of 16B) --
    auto issue = [&](int chunk, int stage) {
        char* base = sm + stage * STAGEB;
        const int k0 = chunk * GBK;
        #pragma unroll
        for (int i = 0; i < 4; ++i) {
            int cc  = tid + i * 256;         // 0..1023
            int row = cc >> 3;               // 0..127
            int q   = cc & 7;                // 16B chunk within 128B row
            uint32_t sa = smem_u32(base + row * ROWB + q * 16);
            const void* ga = Ab + (long long)(bm + row) * K + k0 + q * 8;
            CP_ASYNC16(sa, ga);
            uint32_t sb = smem_u32(base + TILEB + row * ROWB + q * 16);
            const void* gb = Bb + (long long)(bn + row) * K + k0 + q * 8;
            CP_ASYNC16(sb, gb);
        }
    };

    // prologue: fill 2 stages
    issue(0, 0); CP_COMMIT();
    issue(1, 1); CP_COMMIT();

    for (int c = 0; c < NC; ++c) {
        CP_WAIT1();            // chunk c resident
        __syncthreads();       // all warps see it; stage (c+2)%3 fully drained

        // prefetch chunk c+2 into the stage consumed at iter c-1
        const int nc = c + 2;
        if (nc < NC) issue(nc, nc % 3);
        CP_COMMIT();           // empty group in tail keeps bookkeeping uniform

        const int stg = c % 3;
        const uint32_t abase = smem_u32(sm + stg * STAGEB);
        const uint32_t bbase = abase + TILEB;

        #pragma unroll
        for (int ks = 0; ks < 4; ++ks) {
            uint32_t a[4][4], b[2][4];
            #pragma unroll
            for (int t = 0; t < 4; ++t) {
                uint32_t addr = abase
                    + (uint32_t)(wm + t * 16 + (lane & 15)) * ROWB
                    + ks * 32 + ((lane >> 4) << 4);
                LDSM4(a[t], addr);
            }
            #pragma unroll
            for (int u = 0; u < 2; ++u) {
                uint32_t addr = bbase
                    + (uint32_t)(wn + u * 16 + ((lane >> 4) << 3) + (lane & 7)) * ROWB
                    + ks * 32 + (((lane >> 3) & 1) << 4);
                LDSM4(b[u], addr);
            }
            #pragma unroll
            for (int tm = 0; tm < 4; ++tm)
                #pragma unroll
                for (int j = 0; j < 4; ++j)
                    MMA16816(acc[tm][j], a[tm],
                             b[j >> 1][(j & 1) * 2], b[j >> 1][(j & 1) * 2 + 1]);
        }
    }

    // ---- epilogue: direct global stores ----
    const int qr = lane >> 2;            // 0..7
    const int qc = (lane & 3) * 2;       // 0,2,4,6
    #pragma unroll
    for (int tm = 0; tm < 4; ++tm) {
        #pragma unroll
        for (int j = 0; j < 4; ++j) {
            const long long n0 = bn + wn + j * 8 + qc;
            const long long m0 = bm + wm + tm * 16 + qr;
            float b0 = 0.f, b1 = 0.f;
            if (HAS_BIAS) { b0 = bias[n0]; b1 = bias[n0 + 1]; }
            if (OUT == OUT_F16) {
                __half* C = (__half*)Cv + (long long)blockIdx.z * sC;
                __half2 lo = __floats2half2_rn(acc[tm][j][0] + b0, acc[tm][j][1] + b1);
                __half2 hi = __floats2half2_rn(acc[tm][j][2] + b0, acc[tm][j][3] + b1);
                *reinterpret_cast<uint32_t*>(C + m0 * N + n0)       = *reinterpret_cast<uint32_t*>(&lo);
                *reinterpret_cast<uint32_t*>(C + (m0 + 8) * N + n0) = *reinterpret_cast<uint32_t*>(&hi);
            } else {
                float* C = (float*)Cv + (long long)blockIdx.z * sC;
                *reinterpret_cast<float2*>(C + m0 * N + n0) =
                    make_float2(acc[tm][j][0] + b0, acc[tm][j][1] + b1);
                *reinterpret_cast<float2*>(C + (m0 + 8) * N + n0) =
                    make_float2(acc[tm][j][2] + b0, acc[tm][j][3] + b1);
            }
        }
    }
}

// ------- fp32 [R,C] -> fp16 transpose [C,R]; optionally also row-major copy -
template<bool WROW>
__global__ __launch_bounds__(256)
void transpose_h_k(const float* __restrict__ in, __half* __restrict__ outT,
                   __half* __restrict__ outR,
                   int R, int C, long long sIn, long long sOutT, long long sOutR)
{
    __shared__ float t[32][33];
    const float* ib = in + (long long)blockIdx.z * sIn;
    __half* obT = outT + (long long)blockIdx.z * sOutT;
    int c0 = blockIdx.x * 32, r0 = blockIdx.y * 32;
    int tx = threadIdx.x & 31, ty = threadIdx.x >> 5;   // 32 x 8
    #pragma unroll
    for (int j = 0; j < 4; ++j) {
        float v = ib[(long long)(r0 + ty + j * 8) * C + c0 + tx];
        t[ty + j * 8][tx] = v;
        if (WROW) {
            __half* obR = outR + (long long)blockIdx.z * sOutR;
            obR[(long long)(r0 + ty + j * 8) * C + c0 + tx] = __float2half(v);
        }
    }
    __syncthreads();
    #pragma unroll
    for (int j = 0; j < 4; ++j)
        obT[(long long)(c0 + ty + j * 8) * R + r0 + tx] =
            __float2half(t[tx][ty + j * 8]);
}

// ---------------- masked + scaled softmax: fp16 in, fp16 out ---------------
__global__ __launch_bounds__(256)
void softmax_k(const __half* __restrict__ S, __half* __restrict__ P,
               const int* __restrict__ masks, float scale)
{
    const size_t row = blockIdx.x;
    const int b = (int)(row >> 11);               // row / SEQ
    const __half* p = S + row * (size_t)SEQ;
    __half* o = P + row * (size_t)SEQ;
    const int* mrow = masks + (size_t)b * SEQ;
    const int k0 = threadIdx.x * 8;

    __shared__ float red[256];
    float v[8];
    {
        uint4 raw = *reinterpret_cast<const uint4*>(p + k0);
        const __half2* h2 = reinterpret_cast<const __half2*>(&raw);
        int4 m0 = *reinterpret_cast<const int4*>(mrow + k0);
        int4 m1 = *reinterpret_cast<const int4*>(mrow + k0 + 4);
        float2 f;
        f = __half22float2(h2[0]);
        v[0] = m0.x ? f.x * scale : NEG_INF_V;
        v[1] = m0.y ? f.y * scale : NEG_INF_V;
        f = __half22float2(h2[1]);
        v[2] = m0.z ? f.x * scale : NEG_INF_V;
        v[3] = m0.w ? f.y * scale : NEG_INF_V;
        f = __half22float2(h2[2]);
        v[4] = m1.x ? f.x * scale : NEG_INF_V;
        v[5] = m1.y ? f.y * scale : NEG_INF_V;
        f = __half22float2(h2[3]);
        v[6] = m1.z ? f.x * scale : NEG_INF_V;
        v[7] = m1.w ? f.y * scale : NEG_INF_V;
    }
    float mx = -3e38f;
    #pragma unroll
    for (int i = 0; i < 8; ++i) mx = fmaxf(mx, v[i]);
    red[threadIdx.x] = mx;
    __syncthreads();
    #pragma unroll
    for (int s2 = 128; s2 > 0; s2 >>= 1) {
        if (threadIdx.x < s2)
            red[threadIdx.x] = fmaxf(red[threadIdx.x], red[threadIdx.x + s2]);
        __syncthreads();
    }
    mx = red[0];
    __syncthreads();

    float sum = 0.f;
    #pragma unroll
    for (int i = 0; i < 8; ++i) { v[i] = __expf(v[i] - mx); sum += v[i]; }
    red[threadIdx.x] = sum;
    __syncthreads();
    #pragma unroll
    for (int s2 = 128; s2 > 0; s2 >>= 1) {
        if (threadIdx.x < s2) red[threadIdx.x] += red[threadIdx.x + s2];
        __syncthreads();
    }
    const float inv = 1.0f / red[0];

    uint4 pk;
    __half2* ph = reinterpret_cast<__half2*>(&pk);
    ph[0] = __floats2half2_rn(v[0] * inv, v[1] * inv);
    ph[1] = __floats2half2_rn(v[2] * inv, v[3] * inv);
    ph[2] = __floats2half2_rn(v[4] * inv, v[5] * inv);
    ph[3] = __floats2half2_rn(v[6] * inv, v[7] * inv);
    *reinterpret_cast<uint4*>(o + k0) = pk;
}

// ---------------- residual + LayerNorm -------------------------------------
__global__ __launch_bounds__(256)
void ln_k(const float* __restrict__ X, const float* __restrict__ Cx,
          const float* __restrict__ gamma, const float* __restrict__ beta,
          float* __restrict__ out)
{
    const size_t row = blockIdx.x;
    const float* x = X  + row * (size_t)HID;
    const float* c = Cx + row * (size_t)HID;

    __shared__ float red[256];
    float v[4];
    float s = 0.f;
    #pragma unroll
    for (int i = 0; i < 4; ++i) {
        int k = threadIdx.x + i * 256;
        v[i] = x[k] + c[k];
        s += v[i];
    }
    red[threadIdx.x] = s;
    __syncthreads();
    #pragma unroll
    for (int s2 = 128; s2 > 0; s2 >>= 1) {
        if (threadIdx.x < s2) red[threadIdx.x] += red[threadIdx.x + s2];
        __syncthreads();
    }
    const float mu = red[0] * (1.0f / HID);
    __syncthreads();

    float s2v = 0.f;
    #pragma unroll
    for (int i = 0; i < 4; ++i) { float d = v[i] - mu; s2v += d * d; }
    red[threadIdx.x] = s2v;
    __syncthreads();
    #pragma unroll
    for (int s2 = 128; s2 > 0; s2 >>= 1) {
        if (threadIdx.x < s2) red[threadIdx.x] += red[threadIdx.x + s2];
        __syncthreads();
    }
    const float var = red[0] * (1.0f / HID);
    const float r = rsqrtf(var + LN_EPS);
    #pragma unroll
    for (int i = 0; i < 4; ++i) {
        int k = threadIdx.x + i * 256;
        out[row * (size_t)HID + k] = (v[i] - mu) * r * gamma[k] + beta[k];
    }
}

// ---------------- launch ---------------------------------------------------
extern "C" void kernel_launch(void* const* d_in, const int* in_sizes, int n_in,
                              void* d_out, int out_size)
{
    const float* inputs = (const float*)d_in[0];
    const int*   masks  = (const int*)  d_in[1];
    const float* Wq     = (const float*)d_in[2];
    const float* bq     = (const float*)d_in[3];
    const float* Wk     = (const float*)d_in[4];
    const float* bk     = (const float*)d_in[5];
    const float* gamma  = (const float*)d_in[6];
    const float* beta   = (const float*)d_in[7];
    float* out = (float*)d_out;

    __half *Sp, *Pp, *Xbp, *XTp, *Qp, *Kp, *Wqp, *Wkp;
    cudaGetSymbolAddress((void**)&Sp,  g_S);
    cudaGetSymbolAddress((void**)&Pp,  g_P);
    cudaGetSymbolAddress((void**)&Xbp, g_Xb);
    cudaGetSymbolAddress((void**)&XTp, g_XT);
    cudaGetSymbolAddress((void**)&Qp,  g_Qb);
    cudaGetSymbolAddress((void**)&Kp,  g_Kb);
    cudaGetSymbolAddress((void**)&Wqp, g_Wq);
    cudaGetSymbolAddress((void**)&Wkp, g_Wk);
    float* Ctx = (float*)Sp;                         // context reuses scores mem

    const int M = BATCH * SEQ;                       // 16384
    const long long sSH = (long long)SEQ * HID;
    const long long sSS = (long long)SEQ * SEQ;
    const long long sHS = (long long)HID * SEQ;
    const float scale = 0.03125f;                    // 1/sqrt(1024)

    cudaFuncSetAttribute(hgemm<OUT_F16, true >, cudaFuncAttributeMaxDynamicSharedMemorySize, SMEM_GEMM);
    cudaFuncSetAttribute(hgemm<OUT_F16, false>, cudaFuncAttributeMaxDynamicSharedMemorySize, SMEM_GEMM);
    cudaFuncSetAttribute(hgemm<OUT_F32, false>, cudaFuncAttributeMaxDynamicSharedMemorySize, SMEM_GEMM);

    // fp16 conversions / transposes (X: both layouts in one pass)
    transpose_h_k<true ><<<dim3(HID/32, SEQ/32, BATCH), 256>>>(
        inputs, XTp, Xbp, SEQ, HID, sSH, sHS, sSH);
    transpose_h_k<false><<<dim3(HID/32, HID/32, 1), 256>>>(
        Wq, Wqp, nullptr, HID, HID, 0, 0, 0);
    transpose_h_k<false><<<dim3(HID/32, HID/32, 1), 256>>>(
        Wk, Wkp, nullptr, HID, HID, 0, 0, 0);

    // Q = X Wq + bq ; K = X Wk + bk  -> fp16
    hgemm<OUT_F16, true><<<dim3(HID/GBN, M/GBM, 1), 256, SMEM_GEMM>>>(
        Xbp, Wqp, bq, Qp, M, HID, HID, 0, 0, 0);
    hgemm<OUT_F16, true><<<dim3(HID/GBN, M/GBM, 1), 256, SMEM_GEMM>>>(
        Xbp, Wkp, bk, Kp, M, HID, HID, 0, 0, 0);

    // scores = Q K^T per batch -> fp16
    hgemm<OUT_F16, false><<<dim3(SEQ/GBN, SEQ/GBM, BATCH), 256, SMEM_GEMM>>>(
        Qp, Kp, nullptr, Sp, SEQ, SEQ, HID, sSH, sSH, sSS);

    // masked, scaled softmax -> fp16 probs
    softmax_k<<<M, 256>>>(Sp, Pp, masks, scale);

    // context = probs @ X per batch -> fp32 (reuses scores memory)
    hgemm<OUT_F32, false><<<dim3(HID/GBN, SEQ/GBM, BATCH), 256, SMEM_GEMM>>>(
        Pp, XTp, nullptr, Ctx, SEQ, HID, SEQ, sSS, sHS, sSH);

    // out = LN(X + context)
    ln_k<<<M, 256>>>(inputs, Ctx, gamma, beta, out);
}